// round 10
// baseline (speedup 1.0000x reference)
#include <cuda_runtime.h>
#include <cuda_fp16.h>
#include <cstdint>
#include <math.h>

#define HIDDEN 2048
#define SEQ    2048
#define NH     32
#define QKV_COLS 768   // 256 q | 256 k | 256 v
#define CDIM   256     // N_HEADS * V_BITS

// z is stored scaled by 2^20 (fp16 subnormal avoidance); epilogue multiplies by 2^-20
#define Z_SCALE     1048576.0f
#define Z_SCALE_INV 9.5367431640625e-7f

// ---------------- scratch (static device, no allocations) ----------------
__device__ float  g_qkv[SEQ * QKV_COLS];     // tanh(q) | tanh(k) | sigmoid(v)  (f32)
__device__ __half g_z[SEQ * CDIM];           // attn out * 2^20, fp16
__device__ float  g_gate[SEQ * HIDDEN];      // sigmoid(hs @ Wg^T)
// fp16 copies of GEMM inputs
__device__ __half g_hsr[SEQ * HIDDEN];
__device__ __half g_wgr[HIDDEN * HIDDEN];
__device__ __half g_wqkvr[QKV_COLS * HIDDEN];  // Wq | Wk | Wv concatenated
__device__ __half g_wor[HIDDEN * CDIM];
// dependency tracking (reset in preround every call)
__device__ int g_cnt_qkv;
__device__ int g_cnt_attn;
__device__ int g_gflag[256];

// ---------------- helpers ----------------
__device__ __forceinline__ void mma16(float* c, const uint32_t* a, const uint32_t* b) {
    asm volatile(
        "mma.sync.aligned.m16n8k16.row.col.f32.f16.f16.f32 "
        "{%0,%1,%2,%3}, {%4,%5,%6,%7}, {%8,%9}, {%0,%1,%2,%3};\n"
        : "+f"(c[0]), "+f"(c[1]), "+f"(c[2]), "+f"(c[3])
        : "r"(a[0]), "r"(a[1]), "r"(a[2]), "r"(a[3]), "r"(b[0]), "r"(b[1]));
}
__device__ __forceinline__ void ldsm4(uint32_t* d, uint32_t addr) {
    asm volatile("ldmatrix.sync.aligned.m8n8.x4.shared.b16 {%0,%1,%2,%3}, [%4];"
                 : "=r"(d[0]), "=r"(d[1]), "=r"(d[2]), "=r"(d[3]) : "r"(addr));
}
__device__ __forceinline__ void cp16(uint32_t dst, const void* src) {
    asm volatile("cp.async.cg.shared.global [%0], [%1], 16;" :: "r"(dst), "l"(src));
}
__device__ __forceinline__ void cp_commit() { asm volatile("cp.async.commit_group;"); }
template <int N>
__device__ __forceinline__ void cp_wait() { asm volatile("cp.async.wait_group %0;" :: "n"(N)); }

__device__ __forceinline__ float sigm(float x) { return 1.0f / (1.0f + expf(-x)); }
__device__ __forceinline__ int swkey(int r) { return (r & 3) ^ ((r & 4) >> 2); }

// release: all threads fence, sync, tid0 bumps counter / sets flag
__device__ __forceinline__ void dep_release_cnt(int* cnt) {
    __threadfence(); __syncthreads();
    if (threadIdx.x == 0) atomicAdd(cnt, 1);
}
__device__ __forceinline__ void dep_release_flag(int* flag) {
    __threadfence(); __syncthreads();
    if (threadIdx.x == 0) atomicExch(flag, 1);
}
// acquire: tid0 spins, then CTA-wide sync + fence
__device__ __forceinline__ void dep_wait_cnt(const int* cnt, int target) {
    if (threadIdx.x == 0) {
        while (*(volatile const int*)cnt < target) __nanosleep(64);
    }
    __syncthreads(); __threadfence();
}
__device__ __forceinline__ void dep_wait_flag(const int* flag) {
    if (threadIdx.x == 0) {
        while (*(volatile const int*)flag == 0) __nanosleep(64);
    }
    __syncthreads(); __threadfence();
}

// ---------------- GEMM mainloop (NT), fp16 in / f32 acc ----------------
// CTA tile 128x128x32, 8 warps (2x4), warp tile 64x32, m16n8k16, 3-stage cp.async.
constexpr int BM = 128, BN = 128, BK = 32;
constexpr int STAGE = BM * BK * 2;   // 8192 B per operand per stage

__device__ __forceinline__ void gemm_mainloop(
    uint32_t sAb, uint32_t sBb,
    const __half* __restrict__ Ap, int lda,
    const __half* __restrict__ Bp, int ldb,
    int mloc, int nloc, int K, float acc[4][4][4]) {

    const int tid  = threadIdx.x;
    const int warp = tid >> 5, lane = tid & 31;
    const int wm = warp & 1, wn = warp >> 1;

    // producer: row = tid>>1 (0..127), slots s2,s2+1
    const int pr = tid >> 1;
    const int s2 = (tid & 1) * 2;
    const __half* gA = Ap + (size_t)(mloc + pr) * lda + s2 * 8;
    const __half* gB = Bp + (size_t)(nloc + pr) * ldb + s2 * 8;
    const int keyp = swkey(pr);
    const uint32_t pa0 = (uint32_t)(pr * 64 + ((s2     ^ keyp) * 16));
    const uint32_t pa1 = (uint32_t)(pr * 64 + (((s2+1) ^ keyp) * 16));

    // consumer (ldmatrix b16)
    const int l7    = lane & 7;
    const int keyl  = swkey(l7);
    const int a_row = l7 + ((lane >> 3) & 1) * 8;
    const int a_hb  = lane >> 4;
    const int b_row = l7 + (lane >> 4) * 8;
    const int b_hb  = (lane >> 3) & 1;
    uint32_t aBase[4], bBase[2];
#pragma unroll
    for (int mt = 0; mt < 4; mt++)
        aBase[mt] = sAb + (uint32_t)((wm * 64 + mt * 16 + a_row) * 64);
#pragma unroll
    for (int p = 0; p < 2; p++)
        bBase[p] = sBb + (uint32_t)((wn * 32 + p * 16 + b_row) * 64);

    const int nk = K / BK;

#pragma unroll
    for (int p = 0; p < 2; p++) {
        const int off = p * BK;
        const uint32_t sb = (uint32_t)(p * STAGE);
        cp16(sAb + sb + pa0, gA + off);
        cp16(sAb + sb + pa1, gA + off + 8);
        cp16(sBb + sb + pa0, gB + off);
        cp16(sBb + sb + pa1, gB + off + 8);
        cp_commit();
    }

    int st = 0;
    for (int kt = 0; kt < nk; kt++) {
        cp_wait<1>();
        __syncthreads();
        const uint32_t buf = (uint32_t)(st * STAGE);
#pragma unroll
        for (int ks = 0; ks < 2; ks++) {
            uint32_t afr[4][4];
            uint32_t bfr[2][4];
            const uint32_t aslot = (uint32_t)(((2 * ks + a_hb) ^ keyl) * 16);
            const uint32_t bslot = (uint32_t)(((2 * ks + b_hb) ^ keyl) * 16);
#pragma unroll
            for (int mt = 0; mt < 4; mt++)
                ldsm4(afr[mt], aBase[mt] + buf + aslot);
#pragma unroll
            for (int p = 0; p < 2; p++)
                ldsm4(bfr[p], bBase[p] + buf + bslot);
#pragma unroll
            for (int mt = 0; mt < 4; mt++)
#pragma unroll
                for (int nt = 0; nt < 4; nt++)
                    mma16(acc[mt][nt], afr[mt], &bfr[nt >> 1][(nt & 1) * 2]);
        }
        if (kt + 2 < nk) {
            int stp = st + 2; if (stp >= 3) stp -= 3;
            const int off = (kt + 2) * BK;
            const uint32_t sb = (uint32_t)(stp * STAGE);
            cp16(sAb + sb + pa0, gA + off);
            cp16(sAb + sb + pa1, gA + off + 8);
            cp16(sBb + sb + pa0, gB + off);
            cp16(sBb + sb + pa1, gB + off + 8);
        }
        cp_commit();
        if (++st == 3) st = 0;
    }
}

// ---------------- attention params ----------------
constexpr int WIN = 64, QB2 = 256;
constexpr int SROWS2 = QB2 + WIN - 1;   // 319
constexpr int PITCH = 9;

// CTA layout in the megakernel
constexpr int N_QKV  = 96;
constexpr int N_GATE = 256;
constexpr int N_ATTN = 256;             // 8 q-blocks x 32 heads
constexpr int N_OUT  = 256;
constexpr int GRID   = N_QKV + N_GATE + N_ATTN + N_OUT;   // 864

// ---------------- megakernel ----------------
__global__ __launch_bounds__(256, 2)
void mega(const float* __restrict__ e0, const float* __restrict__ e1,
          float* __restrict__ Cout) {
    __shared__ __align__(16) char smem[49152];
    const int cid = blockIdx.x;
    const int tid = threadIdx.x;

    if (cid < N_QKV + N_GATE) {
        // ---------------- GEMM tiles: qkv or gate ----------------
        const uint32_t sAb = (uint32_t)__cvta_generic_to_shared(smem);
        const uint32_t sBb = sAb + 3 * STAGE;

        const bool is_qkv = (cid < N_QKV);
        const __half* Bp;
        int nloc, mloc;
        if (is_qkv) {
            nloc = (cid % 6) * BN;
            mloc = (cid / 6) * BM;
            Bp = g_wqkvr;
        } else {
            const int g = cid - N_QKV;
            nloc = (g & 15) * BN;
            mloc = (g >> 4) * BM;
            Bp = g_wgr;
        }

        float acc[4][4][4];
#pragma unroll
        for (int i = 0; i < 4; i++)
#pragma unroll
            for (int j = 0; j < 4; j++)
#pragma unroll
                for (int l = 0; l < 4; l++) acc[i][j][l] = 0.0f;

        gemm_mainloop(sAb, sBb, g_hsr, HIDDEN, Bp, HIDDEN, mloc, nloc, HIDDEN, acc);

        const int warp = tid >> 5, lane = tid & 31;
        const int g = lane >> 2, t = lane & 3;
        const int wm = warp & 1, wn = warp >> 1;

#pragma unroll
        for (int mt = 0; mt < 4; mt++) {
#pragma unroll
            for (int nt = 0; nt < 4; nt++) {
                const int row0 = mloc + wm * 64 + mt * 16 + g;
                const int col  = nloc + wn * 32 + nt * 8 + 2 * t;
                const float* c = acc[mt][nt];
                if (!is_qkv) {
                    float2 y0, y1;
                    y0.x = sigm(c[0]); y0.y = sigm(c[1]);
                    y1.x = sigm(c[2]); y1.y = sigm(c[3]);
                    *(float2*)&g_gate[row0 * HIDDEN + col] = y0;
                    *(float2*)&g_gate[(row0 + 8) * HIDDEN + col] = y1;
                } else {
                    float2 y0, y1;
                    if (col < 512) {
                        y0.x = tanhf(c[0]); y0.y = tanhf(c[1]);
                        y1.x = tanhf(c[2]); y1.y = tanhf(c[3]);
                    } else {
                        y0.x = sigm(c[0]); y0.y = sigm(c[1]);
                        y1.x = sigm(c[2]); y1.y = sigm(c[3]);
                    }
                    *(float2*)&g_qkv[row0 * QKV_COLS + col] = y0;
                    *(float2*)&g_qkv[(row0 + 8) * QKV_COLS + col] = y1;
                }
            }
        }

        if (is_qkv) dep_release_cnt(&g_cnt_qkv);
        else        dep_release_flag(&g_gflag[cid - N_QKV]);

    } else if (cid < N_QKV + N_GATE + N_ATTN) {
        // ---------------- windowed decayed-softmax attention ----------------
        // decay 0.45 => bias -0.7985*dist; W=64 truncation error < 1e-21 rel.
        dep_wait_cnt(&g_cnt_qkv, N_QKV);

        float* ks = (float*)smem;
        float* vs = ks + SROWS2 * PITCH;

        const int a  = cid - (N_QKV + N_GATE);
        const int h  = a >> 3;                 // 32 heads
        const int q0 = (a & 7) * QB2;          // 8 blocks of 256 rows
        const int j0 = q0 - (WIN - 1);

        for (int idx = tid; idx < SROWS2 * 8; idx += 256) {
            const int r = idx >> 3, c = idx & 7;
            const int j = j0 + r;
            float kv = 0.0f, vv = 0.0f;
            if (j >= 0) {
                kv = g_qkv[j * QKV_COLS + 256 + h * 8 + c];
                vv = g_qkv[j * QKV_COLS + 512 + h * 8 + c];
            }
            ks[r * PITCH + c] = kv;
            vs[r * PITCH + c] = vv;
        }
        __syncthreads();

        const int i = q0 + tid;
        float q[8];
#pragma unroll
        for (int b = 0; b < 8; b++) q[b] = g_qkv[i * QKV_COLS + h * 8 + b];

        float num[8];
#pragma unroll
        for (int b = 0; b < 8; b++) num[b] = 0.0f;
        float den = 0.0f;

        const float LOGD = -0.7985077f;   // ln(0.45)
        const int dmax = (i < WIN - 1) ? i : (WIN - 1);

        for (int d = 0; d <= dmax; d++) {
            const int jj = (tid + (WIN - 1) - d) * PITCH;
            float dot = 0.0f;
#pragma unroll
            for (int b = 0; b < 8; b++) dot += q[b] * ks[jj + b];
            const float w = expf(dot * 0.125f + (float)d * LOGD);
            den += w;
#pragma unroll
            for (int b = 0; b < 8; b++) num[b] += w * vs[jj + b];
        }

        const float inv = 1.0f / den;
#pragma unroll
        for (int b = 0; b < 8; b++) {
            const int c = h * 8 + b;
            const float p = num[b] * inv;
            const float z = e1[c] * p + e0[c] * (1.0f - p);
            g_z[i * CDIM + c] = __float2half_rn(z * Z_SCALE);
        }

        dep_release_cnt(&g_cnt_attn);

    } else {
        // ---------------- OUT tile: out = (z * 2^-20 @ Wo^T) * gate ----------------
        const int o = cid - (N_QKV + N_GATE + N_ATTN);
        dep_wait_flag(&g_gflag[o]);           // matching gate tile done
        dep_wait_cnt(&g_cnt_attn, N_ATTN);    // all of z ready

        const uint32_t sAb = (uint32_t)__cvta_generic_to_shared(smem);
        const uint32_t sBb = sAb + 3 * STAGE;

        const int nloc = (o & 15) * BN;
        const int mloc = (o >> 4) * BM;

        float acc[4][4][4];
#pragma unroll
        for (int i = 0; i < 4; i++)
#pragma unroll
            for (int j = 0; j < 4; j++)
#pragma unroll
                for (int l = 0; l < 4; l++) acc[i][j][l] = 0.0f;

        gemm_mainloop(sAb, sBb, g_z, CDIM, g_wor, CDIM, mloc, nloc, CDIM, acc);

        const int warp = tid >> 5, lane = tid & 31;
        const int g = lane >> 2, t = lane & 3;
        const int wm = warp & 1, wn = warp >> 1;

#pragma unroll
        for (int mt = 0; mt < 4; mt++) {
#pragma unroll
            for (int nt = 0; nt < 4; nt++) {
                const int row0 = mloc + wm * 64 + mt * 16 + g;
                const int col  = nloc + wn * 32 + nt * 8 + 2 * t;
                const float* c = acc[mt][nt];
                float2 gt0 = *(const float2*)&g_gate[row0 * HIDDEN + col];
                float2 gt1 = *(const float2*)&g_gate[(row0 + 8) * HIDDEN + col];
                float2 y0, y1;
                y0.x = c[0] * Z_SCALE_INV * gt0.x; y0.y = c[1] * Z_SCALE_INV * gt0.y;
                y1.x = c[2] * Z_SCALE_INV * gt1.x; y1.y = c[3] * Z_SCALE_INV * gt1.y;
                *(float2*)&Cout[row0 * HIDDEN + col] = y0;
                *(float2*)&Cout[(row0 + 8) * HIDDEN + col] = y1;
            }
        }
    }
}

// ---------------- preround: convert inputs to fp16 once + reset flags ------
__global__ __launch_bounds__(256)
void preround(const float* __restrict__ hs, const float* __restrict__ Wq,
              const float* __restrict__ Wk, const float* __restrict__ Wv,
              const float* __restrict__ Wo, const float* __restrict__ Wg) {
    if (blockIdx.x == 0) {
        if (threadIdx.x == 0) { g_cnt_qkv = 0; g_cnt_attn = 0; }
        g_gflag[threadIdx.x] = 0;   // blockDim 256 covers all flags
    }

    constexpr int N_HS = (SEQ * HIDDEN) / 4;          // float4 groups
    constexpr int N_W  = (256 * HIDDEN) / 4;
    constexpr int TOT  = N_HS * 2 + N_W * 4;          // hs, Wg, Wq, Wk, Wv, Wo

    for (int i = blockIdx.x * blockDim.x + threadIdx.x; i < TOT;
         i += gridDim.x * blockDim.x) {
        const float4* src;
        __half* dst;
        int di;
        if (i < N_HS) {
            src = (const float4*)hs + i;            dst = g_hsr;   di = i;
        } else if (i < 2 * N_HS) {
            src = (const float4*)Wg + (i - N_HS);   dst = g_wgr;   di = i - N_HS;
        } else {
            int j = i - 2 * N_HS;
            if (j < N_W)            { src = (const float4*)Wq + j;           dst = g_wqkvr; di = j; }
            else if (j < 2 * N_W)   { src = (const float4*)Wk + (j - N_W);   dst = g_wqkvr; di = j; }
            else if (j < 3 * N_W)   { src = (const float4*)Wv + (j - 2*N_W); dst = g_wqkvr; di = j; }
            else                    { src = (const float4*)Wo + (j - 3*N_W); dst = g_wor;   di = j - 3*N_W; }
        }
        float4 v = *src;
        __half2 h01 = __floats2half2_rn(v.x, v.y);
        __half2 h23 = __floats2half2_rn(v.z, v.w);
        uint2 u;
        u.x = *(uint32_t*)&h01;
        u.y = *(uint32_t*)&h23;
        *(uint2*)&dst[di * 4] = u;
    }
}

// ---------------- launch ----------------
extern "C" void kernel_launch(void* const* d_in, const int* in_sizes, int n_in,
                              void* d_out, int out_size) {
    const float* hs = (const float*)d_in[0];
    const float* Wq = (const float*)d_in[1];
    const float* Wk = (const float*)d_in[2];
    const float* Wv = (const float*)d_in[3];
    const float* Wo = (const float*)d_in[4];
    const float* Wg = (const float*)d_in[5];
    const float* e0 = (const float*)d_in[6];
    const float* e1 = (const float*)d_in[7];
    float* out = (float*)d_out;

    // 0) convert all GEMM inputs to fp16 once; reset dependency counters
    preround<<<1024, 256>>>(hs, Wq, Wk, Wv, Wo, Wg);

    // 1) everything else: one persistent kernel with tile dependencies
    mega<<<GRID, 256>>>(e0, e1, out);
}

// round 11
// speedup vs baseline: 1.0514x; 1.0514x over previous
#include <cuda_runtime.h>
#include <cuda_fp16.h>
#include <cstdint>
#include <math.h>

#define HIDDEN 2048
#define SEQ    2048
#define NH     32
#define QKV_COLS 768   // 256 q | 256 k | 256 v
#define CDIM   256     // N_HEADS * V_BITS

// z is stored scaled by 2^20 (fp16 subnormal avoidance); epilogue multiplies by 2^-20
#define Z_SCALE     1048576.0f
#define Z_SCALE_INV 9.5367431640625e-7f

// ---------------- scratch (static device, no allocations) ----------------
__device__ float  g_qkv[SEQ * QKV_COLS];     // tanh(q) | tanh(k) | sigmoid(v)  (f32)
__device__ __half g_z[SEQ * CDIM];           // attn out * 2^20, fp16
__device__ float  g_gate[SEQ * HIDDEN];      // sigmoid(hs @ Wg^T)
// fp16 copies of GEMM inputs
__device__ __half g_hsr[SEQ * HIDDEN];
__device__ __half g_wgr[HIDDEN * HIDDEN];
__device__ __half g_wqkvr[QKV_COLS * HIDDEN];  // Wq | Wk | Wv concatenated
__device__ __half g_wor[HIDDEN * CDIM];

// ---------------- helpers ----------------
__device__ __forceinline__ void mma16(float* c, const uint32_t* a, const uint32_t* b) {
    asm volatile(
        "mma.sync.aligned.m16n8k16.row.col.f32.f16.f16.f32 "
        "{%0,%1,%2,%3}, {%4,%5,%6,%7}, {%8,%9}, {%0,%1,%2,%3};\n"
        : "+f"(c[0]), "+f"(c[1]), "+f"(c[2]), "+f"(c[3])
        : "r"(a[0]), "r"(a[1]), "r"(a[2]), "r"(a[3]), "r"(b[0]), "r"(b[1]));
}
__device__ __forceinline__ void ldsm4(uint32_t* d, uint32_t addr) {
    asm volatile("ldmatrix.sync.aligned.m8n8.x4.shared.b16 {%0,%1,%2,%3}, [%4];"
                 : "=r"(d[0]), "=r"(d[1]), "=r"(d[2]), "=r"(d[3]) : "r"(addr));
}
__device__ __forceinline__ void cp16(uint32_t dst, const void* src) {
    asm volatile("cp.async.cg.shared.global [%0], [%1], 16;" :: "r"(dst), "l"(src));
}
__device__ __forceinline__ void cp_commit() { asm volatile("cp.async.commit_group;"); }
template <int N>
__device__ __forceinline__ void cp_wait() { asm volatile("cp.async.wait_group %0;" :: "n"(N)); }

__device__ __forceinline__ float sigm(float x) { return 1.0f / (1.0f + expf(-x)); }
__device__ __forceinline__ int swkey(int r) { return (r & 3) ^ ((r & 4) >> 2); }

// ---------------- GEMM mainloop (NT), fp16 in / f32 acc ----------------
// CTA tile 128x128x32, 8 warps (2x4), warp tile 64x32, m16n8k16, 3-stage cp.async.
// Fragment-level double buffering: group ks+1's ldmatrix issue before group ks's mmas.
constexpr int BM = 128, BN = 128, BK = 32;
constexpr int STAGE = BM * BK * 2;   // 8192 B per operand per stage

__device__ __forceinline__ void gemm_mainloop(
    __half (*As)[BM * BK], __half (*Bs)[BN * BK],
    const __half* __restrict__ Ap, int lda,
    const __half* __restrict__ Bp, int ldb,
    int mloc, int nloc, int K, float acc[4][4][4]) {

    const int tid  = threadIdx.x;
    const int warp = tid >> 5, lane = tid & 31;
    const int wm = warp & 1, wn = warp >> 1;

    // producer: row = tid>>1 (0..127), slots s2,s2+1
    const int pr = tid >> 1;
    const int s2 = (tid & 1) * 2;
    const __half* gA = Ap + (size_t)(mloc + pr) * lda + s2 * 8;
    const __half* gB = Bp + (size_t)(nloc + pr) * ldb + s2 * 8;
    const uint32_t sAb = (uint32_t)__cvta_generic_to_shared(&As[0][0]);
    const uint32_t sBb = (uint32_t)__cvta_generic_to_shared(&Bs[0][0]);
    const int keyp = swkey(pr);
    const uint32_t pa0 = (uint32_t)(pr * 64 + ((s2     ^ keyp) * 16));
    const uint32_t pa1 = (uint32_t)(pr * 64 + (((s2+1) ^ keyp) * 16));

    // consumer (ldmatrix b16)
    const int l7    = lane & 7;
    const int keyl  = swkey(l7);
    const int a_row = l7 + ((lane >> 3) & 1) * 8;
    const int a_hb  = lane >> 4;
    const int b_row = l7 + (lane >> 4) * 8;
    const int b_hb  = (lane >> 3) & 1;
    uint32_t aBase[4], bBase[2];
#pragma unroll
    for (int mt = 0; mt < 4; mt++)
        aBase[mt] = sAb + (uint32_t)((wm * 64 + mt * 16 + a_row) * 64);
#pragma unroll
    for (int p = 0; p < 2; p++)
        bBase[p] = sBb + (uint32_t)((wn * 32 + p * 16 + b_row) * 64);

    const int nk = K / BK;

#pragma unroll
    for (int p = 0; p < 2; p++) {
        const int off = p * BK;
        const uint32_t sb = (uint32_t)(p * STAGE);
        cp16(sAb + sb + pa0, gA + off);
        cp16(sAb + sb + pa1, gA + off + 8);
        cp16(sBb + sb + pa0, gB + off);
        cp16(sBb + sb + pa1, gB + off + 8);
        cp_commit();
    }

    uint32_t afr[2][4][4];
    uint32_t bfr[2][2][4];

    int st = 0;
    for (int kt = 0; kt < nk; kt++) {
        cp_wait<1>();
        __syncthreads();
        const uint32_t buf = (uint32_t)(st * STAGE);

        // prefetch fragments for group 0
        {
            const uint32_t aslot = (uint32_t)(((0 + a_hb) ^ keyl) * 16);
            const uint32_t bslot = (uint32_t)(((0 + b_hb) ^ keyl) * 16);
#pragma unroll
            for (int mt = 0; mt < 4; mt++) ldsm4(afr[0][mt], aBase[mt] + buf + aslot);
#pragma unroll
            for (int p = 0; p < 2; p++)    ldsm4(bfr[0][p], bBase[p] + buf + bslot);
        }
#pragma unroll
        for (int ks = 0; ks < 2; ks++) {
            const int cur = ks & 1, nxt = cur ^ 1;
            if (ks + 1 < 2) {   // prefetch next group's fragments BEFORE mmas
                const uint32_t aslot = (uint32_t)(((2 * (ks + 1) + a_hb) ^ keyl) * 16);
                const uint32_t bslot = (uint32_t)(((2 * (ks + 1) + b_hb) ^ keyl) * 16);
#pragma unroll
                for (int mt = 0; mt < 4; mt++) ldsm4(afr[nxt][mt], aBase[mt] + buf + aslot);
#pragma unroll
                for (int p = 0; p < 2; p++)    ldsm4(bfr[nxt][p], bBase[p] + buf + bslot);
            }
#pragma unroll
            for (int mt = 0; mt < 4; mt++)
#pragma unroll
                for (int nt = 0; nt < 4; nt++)
                    mma16(acc[mt][nt], afr[cur][mt], &bfr[cur][nt >> 1][(nt & 1) * 2]);
        }
        if (kt + 2 < nk) {
            int stp = st + 2; if (stp >= 3) stp -= 3;
            const int off = (kt + 2) * BK;
            const uint32_t sb = (uint32_t)(stp * STAGE);
            cp16(sAb + sb + pa0, gA + off);
            cp16(sAb + sb + pa1, gA + off + 8);
            cp16(sBb + sb + pa0, gB + off);
            cp16(sBb + sb + pa1, gB + off + 8);
        }
        cp_commit();
        if (++st == 3) st = 0;
    }
}

// ---- fused QKV + GATE kernel ----
__global__ __launch_bounds__(256, 2)
void gemm_qkv_gate() {
    __shared__ __half As[3][BM * BK];
    __shared__ __half Bs[3][BN * BK];

    const int cid = blockIdx.x;
    const __half* Bp;
    int nloc, mloc;
    bool is_gate;
    if (cid < 256) {                  // GATE: 16 x 16 tiles
        is_gate = true;
        nloc = (cid & 15) * BN;
        mloc = (cid >> 4) * BM;
        Bp = g_wgr;
    } else {                          // QKV: 6 x 16 tiles over concat [768,2048]
        is_gate = false;
        const int r = cid - 256;
        nloc = (r % 6) * BN;
        mloc = (r / 6) * BM;
        Bp = g_wqkvr;
    }

    float acc[4][4][4];
#pragma unroll
    for (int i = 0; i < 4; i++)
#pragma unroll
        for (int j = 0; j < 4; j++)
#pragma unroll
            for (int l = 0; l < 4; l++) acc[i][j][l] = 0.0f;

    gemm_mainloop(As, Bs, g_hsr, HIDDEN, Bp, HIDDEN, mloc, nloc, HIDDEN, acc);

    const int tid = threadIdx.x;
    const int warp = tid >> 5, lane = tid & 31;
    const int g = lane >> 2, t = lane & 3;
    const int wm = warp & 1, wn = warp >> 1;

#pragma unroll
    for (int mt = 0; mt < 4; mt++) {
#pragma unroll
        for (int nt = 0; nt < 4; nt++) {
            const int row0 = mloc + wm * 64 + mt * 16 + g;
            const int col  = nloc + wn * 32 + nt * 8 + 2 * t;
            const float* c = acc[mt][nt];
            if (is_gate) {
                float2 y0, y1;
                y0.x = sigm(c[0]); y0.y = sigm(c[1]);
                y1.x = sigm(c[2]); y1.y = sigm(c[3]);
                *(float2*)&g_gate[row0 * HIDDEN + col] = y0;
                *(float2*)&g_gate[(row0 + 8) * HIDDEN + col] = y1;
            } else {
                float2 y0, y1;
                if (col < 512) {
                    y0.x = tanhf(c[0]); y0.y = tanhf(c[1]);
                    y1.x = tanhf(c[2]); y1.y = tanhf(c[3]);
                } else {
                    y0.x = sigm(c[0]); y0.y = sigm(c[1]);
                    y1.x = sigm(c[2]); y1.y = sigm(c[3]);
                }
                *(float2*)&g_qkv[row0 * QKV_COLS + col] = y0;
                *(float2*)&g_qkv[(row0 + 8) * QKV_COLS + col] = y1;
            }
        }
    }
}

// ---- OUT kernel: out = (z * 2^-20 @ Wo^T) * gate ----
__global__ __launch_bounds__(256, 2)
void gemm_out(float* __restrict__ Cout) {
    __shared__ __half As[3][BM * BK];
    __shared__ __half Bs[3][BN * BK];

    const int nloc = (blockIdx.x & 15) * BN;
    const int mloc = (blockIdx.x >> 4) * BM;

    float acc[4][4][4];
#pragma unroll
    for (int i = 0; i < 4; i++)
#pragma unroll
        for (int j = 0; j < 4; j++)
#pragma unroll
            for (int l = 0; l < 4; l++) acc[i][j][l] = 0.0f;

    gemm_mainloop(As, Bs, g_z, CDIM, g_wor, CDIM, mloc, nloc, CDIM, acc);

    const int tid = threadIdx.x;
    const int warp = tid >> 5, lane = tid & 31;
    const int g = lane >> 2, t = lane & 3;
    const int wm = warp & 1, wn = warp >> 1;

#pragma unroll
    for (int mt = 0; mt < 4; mt++) {
#pragma unroll
        for (int nt = 0; nt < 4; nt++) {
            const int row0 = mloc + wm * 64 + mt * 16 + g;
            const int col  = nloc + wn * 32 + nt * 8 + 2 * t;
            const float* c = acc[mt][nt];
            float2 gt0 = *(const float2*)&g_gate[row0 * HIDDEN + col];
            float2 gt1 = *(const float2*)&g_gate[(row0 + 8) * HIDDEN + col];
            float2 y0, y1;
            y0.x = c[0] * Z_SCALE_INV * gt0.x; y0.y = c[1] * Z_SCALE_INV * gt0.y;
            y1.x = c[2] * Z_SCALE_INV * gt1.x; y1.y = c[3] * Z_SCALE_INV * gt1.y;
            *(float2*)&Cout[row0 * HIDDEN + col] = y0;
            *(float2*)&Cout[(row0 + 8) * HIDDEN + col] = y1;
        }
    }
}

// ---------------- preround: convert inputs to fp16 once ----------------
__global__ __launch_bounds__(256)
void preround(const float* __restrict__ hs, const float* __restrict__ Wq,
              const float* __restrict__ Wk, const float* __restrict__ Wv,
              const float* __restrict__ Wo, const float* __restrict__ Wg) {
    constexpr int N_HS = (SEQ * HIDDEN) / 4;          // float4 groups
    constexpr int N_W  = (256 * HIDDEN) / 4;
    constexpr int TOT  = N_HS * 2 + N_W * 4;          // hs, Wg, Wq, Wk, Wv, Wo

    for (int i = blockIdx.x * blockDim.x + threadIdx.x; i < TOT;
         i += gridDim.x * blockDim.x) {
        const float4* src;
        __half* dst;
        int di;
        if (i < N_HS) {
            src = (const float4*)hs + i;            dst = g_hsr;   di = i;
        } else if (i < 2 * N_HS) {
            src = (const float4*)Wg + (i - N_HS);   dst = g_wgr;   di = i - N_HS;
        } else {
            int j = i - 2 * N_HS;
            if (j < N_W)            { src = (const float4*)Wq + j;           dst = g_wqkvr; di = j; }
            else if (j < 2 * N_W)   { src = (const float4*)Wk + (j - N_W);   dst = g_wqkvr; di = j; }
            else if (j < 3 * N_W)   { src = (const float4*)Wv + (j - 2*N_W); dst = g_wqkvr; di = j; }
            else                    { src = (const float4*)Wo + (j - 3*N_W); dst = g_wor;   di = j - 3*N_W; }
        }
        float4 v = *src;
        __half2 h01 = __floats2half2_rn(v.x, v.y);
        __half2 h23 = __floats2half2_rn(v.z, v.w);
        uint2 u;
        u.x = *(uint32_t*)&h01;
        u.y = *(uint32_t*)&h23;
        *(uint2*)&dst[di * 4] = u;
    }
}

// ---------------- windowed decayed-softmax attention ----------------
// decay 0.45 => bias -0.7985*dist; truncation at W=64 leaves < 1e-21 relative mass.
constexpr int WIN = 64, QB = 128;
constexpr int SROWS = QB + WIN - 1;   // 191
constexpr int PITCH = 9;              // conflict-free scalar smem reads

__global__ __launch_bounds__(128)
void attn_kernel(const float* __restrict__ e0, const float* __restrict__ e1) {
    __shared__ float ks[SROWS * PITCH];
    __shared__ float vs[SROWS * PITCH];

    const int h   = blockIdx.y;
    const int q0  = blockIdx.x * QB;
    const int tid = threadIdx.x;
    const int j0  = q0 - (WIN - 1);

    for (int idx = tid; idx < SROWS * 8; idx += 128) {
        const int r = idx >> 3, c = idx & 7;
        const int j = j0 + r;
        float kv = 0.0f, vv = 0.0f;
        if (j >= 0) {
            kv = g_qkv[j * QKV_COLS + 256 + h * 8 + c];
            vv = g_qkv[j * QKV_COLS + 512 + h * 8 + c];
        }
        ks[r * PITCH + c] = kv;
        vs[r * PITCH + c] = vv;
    }
    __syncthreads();

    const int i = q0 + tid;
    float q[8];
#pragma unroll
    for (int b = 0; b < 8; b++) q[b] = g_qkv[i * QKV_COLS + h * 8 + b];

    float num[8];
#pragma unroll
    for (int b = 0; b < 8; b++) num[b] = 0.0f;
    float den = 0.0f;

    const float LOGD = -0.7985077f;   // ln(0.45)
    const int dmax = (i < WIN - 1) ? i : (WIN - 1);

    for (int d = 0; d <= dmax; d++) {
        const int jj = (tid + (WIN - 1) - d) * PITCH;
        float dot = 0.0f;
#pragma unroll
        for (int b = 0; b < 8; b++) dot += q[b] * ks[jj + b];
        const float w = expf(dot * 0.125f + (float)d * LOGD);
        den += w;
#pragma unroll
        for (int b = 0; b < 8; b++) num[b] += w * vs[jj + b];
    }

    const float inv = 1.0f / den;
#pragma unroll
    for (int b = 0; b < 8; b++) {
        const int c = h * 8 + b;
        const float p = num[b] * inv;
        const float z = e1[c] * p + e0[c] * (1.0f - p);
        g_z[i * CDIM + c] = __float2half_rn(z * Z_SCALE);
    }
}

// ---------------- launch ----------------
extern "C" void kernel_launch(void* const* d_in, const int* in_sizes, int n_in,
                              void* d_out, int out_size) {
    const float* hs = (const float*)d_in[0];
    const float* Wq = (const float*)d_in[1];
    const float* Wk = (const float*)d_in[2];
    const float* Wv = (const float*)d_in[3];
    const float* Wo = (const float*)d_in[4];
    const float* Wg = (const float*)d_in[5];
    const float* e0 = (const float*)d_in[6];
    const float* e1 = (const float*)d_in[7];
    float* out = (float*)d_out;

    // 0) convert all GEMM inputs to fp16 once
    preround<<<1024, 256>>>(hs, Wq, Wk, Wv, Wo, Wg);

    // 1) fused QKV projections (+activations) and gate GEMM (+sigmoid)
    gemm_qkv_gate<<<256 + 96, 256>>>();

    // 2) windowed attention + value-embedding interpolation
    attn_kernel<<<dim3(SEQ / QB, NH), 128>>>(e0, e1);

    // 3) out = (z @ Wo^T) * 2^-20 * gate
    gemm_out<<<256, 256>>>(out);
}

// round 12
// speedup vs baseline: 1.1279x; 1.0728x over previous
#include <cuda_runtime.h>
#include <cuda_fp16.h>
#include <cstdint>
#include <math.h>

#define HIDDEN 2048
#define SEQ    2048
#define NH     32
#define QKV_COLS 768   // 256 q | 256 k | 256 v
#define CDIM   256     // N_HEADS * V_BITS

// z is stored scaled by 2^20 (fp16 subnormal avoidance); epilogue multiplies by 2^-20
#define Z_SCALE     1048576.0f
#define Z_SCALE_INV 9.5367431640625e-7f

// ---------------- scratch (static device, no allocations) ----------------
__device__ float  g_qkv[SEQ * QKV_COLS];     // tanh(q) | tanh(k) | sigmoid(v)  (f32)
__device__ __half g_z[SEQ * CDIM];           // attn out * 2^20, fp16
__device__ float  g_gate[SEQ * HIDDEN];      // sigmoid(hs @ Wg^T)
// fp16 copies of GEMM inputs
__device__ __half g_hsr[SEQ * HIDDEN];
__device__ __half g_wgr[HIDDEN * HIDDEN];
__device__ __half g_wqkvr[QKV_COLS * HIDDEN];  // Wq | Wk | Wv concatenated
__device__ __half g_wor[HIDDEN * CDIM];

// ---------------- helpers ----------------
__device__ __forceinline__ void mma16(float* c, const uint32_t* a, const uint32_t* b) {
    asm volatile(
        "mma.sync.aligned.m16n8k16.row.col.f32.f16.f16.f32 "
        "{%0,%1,%2,%3}, {%4,%5,%6,%7}, {%8,%9}, {%0,%1,%2,%3};\n"
        : "+f"(c[0]), "+f"(c[1]), "+f"(c[2]), "+f"(c[3])
        : "r"(a[0]), "r"(a[1]), "r"(a[2]), "r"(a[3]), "r"(b[0]), "r"(b[1]));
}
__device__ __forceinline__ void ldsm4(uint32_t* d, uint32_t addr) {
    asm volatile("ldmatrix.sync.aligned.m8n8.x4.shared.b16 {%0,%1,%2,%3}, [%4];"
                 : "=r"(d[0]), "=r"(d[1]), "=r"(d[2]), "=r"(d[3]) : "r"(addr));
}
__device__ __forceinline__ void cp16(uint32_t dst, const void* src) {
    asm volatile("cp.async.cg.shared.global [%0], [%1], 16;" :: "r"(dst), "l"(src));
}
__device__ __forceinline__ void cp_commit() { asm volatile("cp.async.commit_group;"); }
template <int N>
__device__ __forceinline__ void cp_wait() { asm volatile("cp.async.wait_group %0;" :: "n"(N)); }

__device__ __forceinline__ float sigm(float x) { return 1.0f / (1.0f + expf(-x)); }
__device__ __forceinline__ int swkey(int r) { return (r & 3) ^ ((r & 4) >> 2); }

// ---------------- GEMM mainloop (NT), fp16 in / f32 acc ----------------
// CTA tile (MT*32) x 128 x 32, 8 warps (2m x 4n), warp tile (MT*16) x 32, m16n8k16.
// 3-stage cp.async. MT=4 -> BM=128 (acc[4]); MT=2 -> BM=64 (acc[2]).
constexpr int BN = 128, BK = 32;
constexpr int BSTAGE = 128 * 64;     // 8192 B per B stage

template <int MT>
__device__ __forceinline__ void gemm_mainloop(
    uint32_t sAb, uint32_t sBb,
    const __half* __restrict__ Ap, int lda,
    const __half* __restrict__ Bp, int ldb,
    int mloc, int nloc, int K, float acc[MT][4][4]) {

    constexpr int BMt = MT * 32;
    constexpr int ASTAGE = BMt * 64;

    const int tid  = threadIdx.x;
    const int warp = tid >> 5, lane = tid & 31;
    const int wm = warp & 1, wn = warp >> 1;

    // ---- producer A ----
    const int apr = (MT == 4) ? (tid >> 1) : (tid >> 2);
    const int as0 = (MT == 4) ? ((tid & 1) * 2) : (tid & 3);
    const __half* gA = Ap + (size_t)(mloc + apr) * lda + as0 * 8;
    const int keypa = swkey(apr);
    const uint32_t paa0 = (uint32_t)(apr * 64 + ((as0 ^ keypa) * 16));
    const uint32_t paa1 = (uint32_t)(apr * 64 + (((as0 + 1) ^ keypa) * 16));  // MT==4 only

    // ---- producer B ----
    const int bpr = tid >> 1;
    const int bs0 = (tid & 1) * 2;
    const __half* gB = Bp + (size_t)(nloc + bpr) * ldb + bs0 * 8;
    const int keypb = swkey(bpr);
    const uint32_t pb0 = (uint32_t)(bpr * 64 + ((bs0 ^ keypb) * 16));
    const uint32_t pb1 = (uint32_t)(bpr * 64 + (((bs0 + 1) ^ keypb) * 16));

    // ---- consumer (ldmatrix b16) ----
    const int l7    = lane & 7;
    const int keyl  = swkey(l7);
    const int a_row = l7 + ((lane >> 3) & 1) * 8;
    const int a_hb  = lane >> 4;
    const int b_row = l7 + (lane >> 4) * 8;
    const int b_hb  = (lane >> 3) & 1;
    uint32_t aBase[MT], bBase[2];
#pragma unroll
    for (int mt = 0; mt < MT; mt++)
        aBase[mt] = sAb + (uint32_t)((wm * (MT * 16) + mt * 16 + a_row) * 64);
#pragma unroll
    for (int p = 0; p < 2; p++)
        bBase[p] = sBb + (uint32_t)((wn * 32 + p * 16 + b_row) * 64);

    const int nk = K / BK;

#pragma unroll
    for (int p = 0; p < 2; p++) {
        const int off = p * BK;
        cp16(sAb + (uint32_t)(p * ASTAGE) + paa0, gA + off);
        if (MT == 4) cp16(sAb + (uint32_t)(p * ASTAGE) + paa1, gA + off + 8);
        cp16(sBb + (uint32_t)(p * BSTAGE) + pb0, gB + off);
        cp16(sBb + (uint32_t)(p * BSTAGE) + pb1, gB + off + 8);
        cp_commit();
    }

    int st = 0;
    for (int kt = 0; kt < nk; kt++) {
        cp_wait<1>();
        __syncthreads();
        const uint32_t abuf = (uint32_t)(st * ASTAGE);
        const uint32_t bbuf = (uint32_t)(st * BSTAGE);
#pragma unroll
        for (int ks = 0; ks < 2; ks++) {
            uint32_t afr[MT][4];
            uint32_t bfr[2][4];
            const uint32_t aslot = (uint32_t)(((2 * ks + a_hb) ^ keyl) * 16);
            const uint32_t bslot = (uint32_t)(((2 * ks + b_hb) ^ keyl) * 16);
#pragma unroll
            for (int mt = 0; mt < MT; mt++)
                ldsm4(afr[mt], aBase[mt] + abuf + aslot);
#pragma unroll
            for (int p = 0; p < 2; p++)
                ldsm4(bfr[p], bBase[p] + bbuf + bslot);
#pragma unroll
            for (int mt = 0; mt < MT; mt++)
#pragma unroll
                for (int nt = 0; nt < 4; nt++)
                    mma16(acc[mt][nt], afr[mt], &bfr[nt >> 1][(nt & 1) * 2]);
        }
        if (kt + 2 < nk) {
            int stp = st + 2; if (stp >= 3) stp -= 3;
            const int off = (kt + 2) * BK;
            cp16(sAb + (uint32_t)(stp * ASTAGE) + paa0, gA + off);
            if (MT == 4) cp16(sAb + (uint32_t)(stp * ASTAGE) + paa1, gA + off + 8);
            cp16(sBb + (uint32_t)(stp * BSTAGE) + pb0, gB + off);
            cp16(sBb + (uint32_t)(stp * BSTAGE) + pb1, gB + off + 8);
        }
        cp_commit();
        if (++st == 3) st = 0;
    }
}

// ---- fused QKV + GATE kernel: BM=64 tiles, 3 CTAs/SM, single-ish wave ----
__global__ __launch_bounds__(256, 3)
void gemm_qkv_gate() {
    __shared__ __half As[3][64 * BK];    // 12 KB
    __shared__ __half Bs[3][128 * BK];   // 24 KB

    const uint32_t sAb = (uint32_t)__cvta_generic_to_shared(&As[0][0]);
    const uint32_t sBb = (uint32_t)__cvta_generic_to_shared(&Bs[0][0]);

    const int cid = blockIdx.x;
    const __half* Bp;
    int nloc, mloc;
    bool is_gate;
    if (cid < 512) {                  // GATE: 32 (m) x 16 (n) tiles
        is_gate = true;
        nloc = (cid & 15) * BN;
        mloc = (cid >> 4) * 64;
        Bp = g_wgr;
    } else {                          // QKV: 32 (m) x 6 (n) tiles
        is_gate = false;
        const int r = cid - 512;
        nloc = (r % 6) * BN;
        mloc = (r / 6) * 64;
        Bp = g_wqkvr;
    }

    float acc[2][4][4];
#pragma unroll
    for (int i = 0; i < 2; i++)
#pragma unroll
        for (int j = 0; j < 4; j++)
#pragma unroll
            for (int l = 0; l < 4; l++) acc[i][j][l] = 0.0f;

    gemm_mainloop<2>(sAb, sBb, g_hsr, HIDDEN, Bp, HIDDEN, mloc, nloc, HIDDEN, acc);

    const int tid = threadIdx.x;
    const int warp = tid >> 5, lane = tid & 31;
    const int g = lane >> 2, t = lane & 3;
    const int wm = warp & 1, wn = warp >> 1;

#pragma unroll
    for (int mt = 0; mt < 2; mt++) {
#pragma unroll
        for (int nt = 0; nt < 4; nt++) {
            const int row0 = mloc + wm * 32 + mt * 16 + g;
            const int col  = nloc + wn * 32 + nt * 8 + 2 * t;
            const float* c = acc[mt][nt];
            if (is_gate) {
                float2 y0, y1;
                y0.x = sigm(c[0]); y0.y = sigm(c[1]);
                y1.x = sigm(c[2]); y1.y = sigm(c[3]);
                *(float2*)&g_gate[row0 * HIDDEN + col] = y0;
                *(float2*)&g_gate[(row0 + 8) * HIDDEN + col] = y1;
            } else {
                float2 y0, y1;
                if (col < 512) {
                    y0.x = tanhf(c[0]); y0.y = tanhf(c[1]);
                    y1.x = tanhf(c[2]); y1.y = tanhf(c[3]);
                } else {
                    y0.x = sigm(c[0]); y0.y = sigm(c[1]);
                    y1.x = sigm(c[2]); y1.y = sigm(c[3]);
                }
                *(float2*)&g_qkv[row0 * QKV_COLS + col] = y0;
                *(float2*)&g_qkv[(row0 + 8) * QKV_COLS + col] = y1;
            }
        }
    }
}

// ---- OUT kernel: out = (z * 2^-20 @ Wo^T) * gate  (proven R9 config) ----
__global__ __launch_bounds__(256, 2)
void gemm_out(float* __restrict__ Cout) {
    __shared__ __half As[3][128 * BK];
    __shared__ __half Bs[3][128 * BK];

    const uint32_t sAb = (uint32_t)__cvta_generic_to_shared(&As[0][0]);
    const uint32_t sBb = (uint32_t)__cvta_generic_to_shared(&Bs[0][0]);

    const int nloc = (blockIdx.x & 15) * BN;
    const int mloc = (blockIdx.x >> 4) * 128;

    float acc[4][4][4];
#pragma unroll
    for (int i = 0; i < 4; i++)
#pragma unroll
        for (int j = 0; j < 4; j++)
#pragma unroll
            for (int l = 0; l < 4; l++) acc[i][j][l] = 0.0f;

    gemm_mainloop<4>(sAb, sBb, g_z, CDIM, g_wor, CDIM, mloc, nloc, CDIM, acc);

    const int tid = threadIdx.x;
    const int warp = tid >> 5, lane = tid & 31;
    const int g = lane >> 2, t = lane & 3;
    const int wm = warp & 1, wn = warp >> 1;

#pragma unroll
    for (int mt = 0; mt < 4; mt++) {
#pragma unroll
        for (int nt = 0; nt < 4; nt++) {
            const int row0 = mloc + wm * 64 + mt * 16 + g;
            const int col  = nloc + wn * 32 + nt * 8 + 2 * t;
            const float* c = acc[mt][nt];
            float2 gt0 = *(const float2*)&g_gate[row0 * HIDDEN + col];
            float2 gt1 = *(const float2*)&g_gate[(row0 + 8) * HIDDEN + col];
            float2 y0, y1;
            y0.x = c[0] * Z_SCALE_INV * gt0.x; y0.y = c[1] * Z_SCALE_INV * gt0.y;
            y1.x = c[2] * Z_SCALE_INV * gt1.x; y1.y = c[3] * Z_SCALE_INV * gt1.y;
            *(float2*)&Cout[row0 * HIDDEN + col] = y0;
            *(float2*)&Cout[(row0 + 8) * HIDDEN + col] = y1;
        }
    }
}

// ---------------- preround: convert inputs to fp16 once ----------------
__global__ __launch_bounds__(256)
void preround(const float* __restrict__ hs, const float* __restrict__ Wq,
              const float* __restrict__ Wk, const float* __restrict__ Wv,
              const float* __restrict__ Wo, const float* __restrict__ Wg) {
    constexpr int N_HS = (SEQ * HIDDEN) / 4;          // float4 groups
    constexpr int N_W  = (256 * HIDDEN) / 4;
    constexpr int TOT  = N_HS * 2 + N_W * 4;          // hs, Wg, Wq, Wk, Wv, Wo

    for (int i = blockIdx.x * blockDim.x + threadIdx.x; i < TOT;
         i += gridDim.x * blockDim.x) {
        const float4* src;
        __half* dst;
        int di;
        if (i < N_HS) {
            src = (const float4*)hs + i;            dst = g_hsr;   di = i;
        } else if (i < 2 * N_HS) {
            src = (const float4*)Wg + (i - N_HS);   dst = g_wgr;   di = i - N_HS;
        } else {
            int j = i - 2 * N_HS;
            if (j < N_W)            { src = (const float4*)Wq + j;           dst = g_wqkvr; di = j; }
            else if (j < 2 * N_W)   { src = (const float4*)Wk + (j - N_W);   dst = g_wqkvr; di = j; }
            else if (j < 3 * N_W)   { src = (const float4*)Wv + (j - 2*N_W); dst = g_wqkvr; di = j; }
            else                    { src = (const float4*)Wo + (j - 3*N_W); dst = g_wor;   di = j - 3*N_W; }
        }
        float4 v = *src;
        __half2 h01 = __floats2half2_rn(v.x, v.y);
        __half2 h23 = __floats2half2_rn(v.z, v.w);
        uint2 u;
        u.x = *(uint32_t*)&h01;
        u.y = *(uint32_t*)&h23;
        *(uint2*)&dst[di * 4] = u;
    }
}

// ---------------- windowed decayed-softmax attention ----------------
// decay 0.45 => bias -0.7985*dist; truncation at W=64 leaves < 1e-21 relative mass.
constexpr int WIN = 64, QB = 128;
constexpr int SROWS = QB + WIN - 1;   // 191
constexpr int PITCH = 9;              // conflict-free scalar smem reads

__global__ __launch_bounds__(128)
void attn_kernel(const float* __restrict__ e0, const float* __restrict__ e1) {
    __shared__ float ks[SROWS * PITCH];
    __shared__ float vs[SROWS * PITCH];

    const int h   = blockIdx.y;
    const int q0  = blockIdx.x * QB;
    const int tid = threadIdx.x;
    const int j0  = q0 - (WIN - 1);

    for (int idx = tid; idx < SROWS * 8; idx += 128) {
        const int r = idx >> 3, c = idx & 7;
        const int j = j0 + r;
        float kv = 0.0f, vv = 0.0f;
        if (j >= 0) {
            kv = g_qkv[j * QKV_COLS + 256 + h * 8 + c];
            vv = g_qkv[j * QKV_COLS + 512 + h * 8 + c];
        }
        ks[r * PITCH + c] = kv;
        vs[r * PITCH + c] = vv;
    }
    __syncthreads();

    const int i = q0 + tid;
    float q[8];
#pragma unroll
    for (int b = 0; b < 8; b++) q[b] = g_qkv[i * QKV_COLS + h * 8 + b];

    float num[8];
#pragma unroll
    for (int b = 0; b < 8; b++) num[b] = 0.0f;
    float den = 0.0f;

    const float LOGD = -0.7985077f;   // ln(0.45)
    const int dmax = (i < WIN - 1) ? i : (WIN - 1);

    for (int d = 0; d <= dmax; d++) {
        const int jj = (tid + (WIN - 1) - d) * PITCH;
        float dot = 0.0f;
#pragma unroll
        for (int b = 0; b < 8; b++) dot += q[b] * ks[jj + b];
        const float w = expf(dot * 0.125f + (float)d * LOGD);
        den += w;
#pragma unroll
        for (int b = 0; b < 8; b++) num[b] += w * vs[jj + b];
    }

    const float inv = 1.0f / den;
#pragma unroll
    for (int b = 0; b < 8; b++) {
        const int c = h * 8 + b;
        const float p = num[b] * inv;
        const float z = e1[c] * p + e0[c] * (1.0f - p);
        g_z[i * CDIM + c] = __float2half_rn(z * Z_SCALE);
    }
}

// ---------------- launch ----------------
extern "C" void kernel_launch(void* const* d_in, const int* in_sizes, int n_in,
                              void* d_out, int out_size) {
    const float* hs = (const float*)d_in[0];
    const float* Wq = (const float*)d_in[1];
    const float* Wk = (const float*)d_in[2];
    const float* Wv = (const float*)d_in[3];
    const float* Wo = (const float*)d_in[4];
    const float* Wg = (const float*)d_in[5];
    const float* e0 = (const float*)d_in[6];
    const float* e1 = (const float*)d_in[7];
    float* out = (float*)d_out;

    // 0) convert all GEMM inputs to fp16 once
    preround<<<1024, 256>>>(hs, Wq, Wk, Wv, Wo, Wg);

    // 1) fused QKV projections (+activations) and gate GEMM (+sigmoid)
    //    BM=64 tiles: 512 gate + 192 qkv = 704 CTAs over ~444 slots (occ 3)
    gemm_qkv_gate<<<512 + 192, 256>>>();

    // 2) windowed attention + value-embedding interpolation
    attn_kernel<<<dim3(SEQ / QB, NH), 128>>>(e0, e1);

    // 3) out = (z @ Wo^T) * 2^-20 * gate
    gemm_out<<<256, 256>>>(out);
}

// round 13
// speedup vs baseline: 1.1586x; 1.0273x over previous
#include <cuda_runtime.h>
#include <cuda_fp16.h>
#include <cstdint>
#include <math.h>

#define HIDDEN 2048
#define SEQ    2048
#define NH     32
#define QKV_COLS 768   // 256 q | 256 k | 256 v
#define CDIM   256     // N_HEADS * V_BITS

// z is stored scaled by 2^20 (fp16 subnormal avoidance); epilogue multiplies by 2^-20
#define Z_SCALE     1048576.0f
#define Z_SCALE_INV 9.5367431640625e-7f

// ---------------- scratch (static device, no allocations) ----------------
__device__ __half g_qkv[SEQ * QKV_COLS];     // tanh(q) | tanh(k) | sigmoid(v)  (fp16)
__device__ __half g_z[SEQ * CDIM];           // attn out * 2^20, fp16
__device__ __half g_gate[SEQ * HIDDEN];      // sigmoid(hs @ Wg^T), fp16
// fp16 copies of GEMM inputs
__device__ __half g_hsr[SEQ * HIDDEN];
__device__ __half g_wgr[HIDDEN * HIDDEN];
__device__ __half g_wqkvr[QKV_COLS * HIDDEN];  // Wq | Wk | Wv concatenated
__device__ __half g_wor[HIDDEN * CDIM];

// ---------------- helpers ----------------
__device__ __forceinline__ void mma16(float* c, const uint32_t* a, const uint32_t* b) {
    asm volatile(
        "mma.sync.aligned.m16n8k16.row.col.f32.f16.f16.f32 "
        "{%0,%1,%2,%3}, {%4,%5,%6,%7}, {%8,%9}, {%0,%1,%2,%3};\n"
        : "+f"(c[0]), "+f"(c[1]), "+f"(c[2]), "+f"(c[3])
        : "r"(a[0]), "r"(a[1]), "r"(a[2]), "r"(a[3]), "r"(b[0]), "r"(b[1]));
}
__device__ __forceinline__ void ldsm4(uint32_t* d, uint32_t addr) {
    asm volatile("ldmatrix.sync.aligned.m8n8.x4.shared.b16 {%0,%1,%2,%3}, [%4];"
                 : "=r"(d[0]), "=r"(d[1]), "=r"(d[2]), "=r"(d[3]) : "r"(addr));
}
__device__ __forceinline__ void cp16(uint32_t dst, const void* src) {
    asm volatile("cp.async.cg.shared.global [%0], [%1], 16;" :: "r"(dst), "l"(src));
}
__device__ __forceinline__ void cp_commit() { asm volatile("cp.async.commit_group;"); }
template <int N>
__device__ __forceinline__ void cp_wait() { asm volatile("cp.async.wait_group %0;" :: "n"(N)); }

__device__ __forceinline__ float sigm(float x) { return 1.0f / (1.0f + expf(-x)); }
__device__ __forceinline__ int swkey(int r) { return (r & 3) ^ ((r & 4) >> 2); }

__device__ __forceinline__ uint32_t pack_h2(float a, float b) {
    __half2 h = __floats2half2_rn(a, b);
    return *(uint32_t*)&h;
}

// ---------------- GEMM mainloop (NT), fp16 in / f32 acc ----------------
// CTA tile (MT*32) x 128 x 32, 8 warps (2m x 4n), warp tile (MT*16) x 32, m16n8k16.
// 3-stage cp.async. MT=4 -> BM=128 (acc[4]); MT=2 -> BM=64 (acc[2]).
constexpr int BN = 128, BK = 32;
constexpr int BSTAGE = 128 * 64;     // 8192 B per B stage

template <int MT>
__device__ __forceinline__ void gemm_mainloop(
    uint32_t sAb, uint32_t sBb,
    const __half* __restrict__ Ap, int lda,
    const __half* __restrict__ Bp, int ldb,
    int mloc, int nloc, int K, float acc[MT][4][4]) {

    constexpr int BMt = MT * 32;
    constexpr int ASTAGE = BMt * 64;

    const int tid  = threadIdx.x;
    const int warp = tid >> 5, lane = tid & 31;
    const int wm = warp & 1, wn = warp >> 1;

    // ---- producer A ----
    const int apr = (MT == 4) ? (tid >> 1) : (tid >> 2);
    const int as0 = (MT == 4) ? ((tid & 1) * 2) : (tid & 3);
    const __half* gA = Ap + (size_t)(mloc + apr) * lda + as0 * 8;
    const int keypa = swkey(apr);
    const uint32_t paa0 = (uint32_t)(apr * 64 + ((as0 ^ keypa) * 16));
    const uint32_t paa1 = (uint32_t)(apr * 64 + (((as0 + 1) ^ keypa) * 16));  // MT==4 only

    // ---- producer B ----
    const int bpr = tid >> 1;
    const int bs0 = (tid & 1) * 2;
    const __half* gB = Bp + (size_t)(nloc + bpr) * ldb + bs0 * 8;
    const int keypb = swkey(bpr);
    const uint32_t pb0 = (uint32_t)(bpr * 64 + ((bs0 ^ keypb) * 16));
    const uint32_t pb1 = (uint32_t)(bpr * 64 + (((bs0 + 1) ^ keypb) * 16));

    // ---- consumer (ldmatrix b16) ----
    const int l7    = lane & 7;
    const int keyl  = swkey(l7);
    const int a_row = l7 + ((lane >> 3) & 1) * 8;
    const int a_hb  = lane >> 4;
    const int b_row = l7 + (lane >> 4) * 8;
    const int b_hb  = (lane >> 3) & 1;
    uint32_t aBase[MT], bBase[2];
#pragma unroll
    for (int mt = 0; mt < MT; mt++)
        aBase[mt] = sAb + (uint32_t)((wm * (MT * 16) + mt * 16 + a_row) * 64);
#pragma unroll
    for (int p = 0; p < 2; p++)
        bBase[p] = sBb + (uint32_t)((wn * 32 + p * 16 + b_row) * 64);

    const int nk = K / BK;

#pragma unroll
    for (int p = 0; p < 2; p++) {
        const int off = p * BK;
        cp16(sAb + (uint32_t)(p * ASTAGE) + paa0, gA + off);
        if (MT == 4) cp16(sAb + (uint32_t)(p * ASTAGE) + paa1, gA + off + 8);
        cp16(sBb + (uint32_t)(p * BSTAGE) + pb0, gB + off);
        cp16(sBb + (uint32_t)(p * BSTAGE) + pb1, gB + off + 8);
        cp_commit();
    }

    int st = 0;
    for (int kt = 0; kt < nk; kt++) {
        cp_wait<1>();
        __syncthreads();
        const uint32_t abuf = (uint32_t)(st * ASTAGE);
        const uint32_t bbuf = (uint32_t)(st * BSTAGE);
#pragma unroll
        for (int ks = 0; ks < 2; ks++) {
            uint32_t afr[MT][4];
            uint32_t bfr[2][4];
            const uint32_t aslot = (uint32_t)(((2 * ks + a_hb) ^ keyl) * 16);
            const uint32_t bslot = (uint32_t)(((2 * ks + b_hb) ^ keyl) * 16);
#pragma unroll
            for (int mt = 0; mt < MT; mt++)
                ldsm4(afr[mt], aBase[mt] + abuf + aslot);
#pragma unroll
            for (int p = 0; p < 2; p++)
                ldsm4(bfr[p], bBase[p] + bbuf + bslot);
#pragma unroll
            for (int mt = 0; mt < MT; mt++)
#pragma unroll
                for (int nt = 0; nt < 4; nt++)
                    mma16(acc[mt][nt], afr[mt], &bfr[nt >> 1][(nt & 1) * 2]);
        }
        if (kt + 2 < nk) {
            int stp = st + 2; if (stp >= 3) stp -= 3;
            const int off = (kt + 2) * BK;
            cp16(sAb + (uint32_t)(stp * ASTAGE) + paa0, gA + off);
            if (MT == 4) cp16(sAb + (uint32_t)(stp * ASTAGE) + paa1, gA + off + 8);
            cp16(sBb + (uint32_t)(stp * BSTAGE) + pb0, gB + off);
            cp16(sBb + (uint32_t)(stp * BSTAGE) + pb1, gB + off + 8);
        }
        cp_commit();
        if (++st == 3) st = 0;
    }
}

// ---- fused QKV + GATE kernel: BM=64 tiles, 3 CTAs/SM ----
__global__ __launch_bounds__(256, 3)
void gemm_qkv_gate() {
    __shared__ __half As[3][64 * BK];    // 12 KB
    __shared__ __half Bs[3][128 * BK];   // 24 KB

    const uint32_t sAb = (uint32_t)__cvta_generic_to_shared(&As[0][0]);
    const uint32_t sBb = (uint32_t)__cvta_generic_to_shared(&Bs[0][0]);

    const int cid = blockIdx.x;
    const __half* Bp;
    int nloc, mloc;
    bool is_gate;
    if (cid < 512) {                  // GATE: 32 (m) x 16 (n) tiles
        is_gate = true;
        nloc = (cid & 15) * BN;
        mloc = (cid >> 4) * 64;
        Bp = g_wgr;
    } else {                          // QKV: 32 (m) x 6 (n) tiles
        is_gate = false;
        const int r = cid - 512;
        nloc = (r % 6) * BN;
        mloc = (r / 6) * 64;
        Bp = g_wqkvr;
    }

    float acc[2][4][4];
#pragma unroll
    for (int i = 0; i < 2; i++)
#pragma unroll
        for (int j = 0; j < 4; j++)
#pragma unroll
            for (int l = 0; l < 4; l++) acc[i][j][l] = 0.0f;

    gemm_mainloop<2>(sAb, sBb, g_hsr, HIDDEN, Bp, HIDDEN, mloc, nloc, HIDDEN, acc);

    const int tid = threadIdx.x;
    const int warp = tid >> 5, lane = tid & 31;
    const int g = lane >> 2, t = lane & 3;
    const int wm = warp & 1, wn = warp >> 1;

#pragma unroll
    for (int mt = 0; mt < 2; mt++) {
#pragma unroll
        for (int nt = 0; nt < 4; nt++) {
            const int row0 = mloc + wm * 32 + mt * 16 + g;
            const int col  = nloc + wn * 32 + nt * 8 + 2 * t;
            const float* c = acc[mt][nt];
            if (is_gate) {
                *(uint32_t*)&g_gate[row0 * HIDDEN + col]       = pack_h2(sigm(c[0]), sigm(c[1]));
                *(uint32_t*)&g_gate[(row0 + 8) * HIDDEN + col] = pack_h2(sigm(c[2]), sigm(c[3]));
            } else {
                uint32_t y0, y1;
                if (col < 512) {
                    y0 = pack_h2(tanhf(c[0]), tanhf(c[1]));
                    y1 = pack_h2(tanhf(c[2]), tanhf(c[3]));
                } else {
                    y0 = pack_h2(sigm(c[0]), sigm(c[1]));
                    y1 = pack_h2(sigm(c[2]), sigm(c[3]));
                }
                *(uint32_t*)&g_qkv[row0 * QKV_COLS + col]       = y0;
                *(uint32_t*)&g_qkv[(row0 + 8) * QKV_COLS + col] = y1;
            }
        }
    }
}

// ---- OUT kernel: out = (z * 2^-20 @ Wo^T) * gate ----
__global__ __launch_bounds__(256, 2)
void gemm_out(float* __restrict__ Cout) {
    __shared__ __half As[3][128 * BK];
    __shared__ __half Bs[3][128 * BK];

    const uint32_t sAb = (uint32_t)__cvta_generic_to_shared(&As[0][0]);
    const uint32_t sBb = (uint32_t)__cvta_generic_to_shared(&Bs[0][0]);

    const int nloc = (blockIdx.x & 15) * BN;
    const int mloc = (blockIdx.x >> 4) * 128;

    float acc[4][4][4];
#pragma unroll
    for (int i = 0; i < 4; i++)
#pragma unroll
        for (int j = 0; j < 4; j++)
#pragma unroll
            for (int l = 0; l < 4; l++) acc[i][j][l] = 0.0f;

    gemm_mainloop<4>(sAb, sBb, g_z, CDIM, g_wor, CDIM, mloc, nloc, CDIM, acc);

    const int tid = threadIdx.x;
    const int warp = tid >> 5, lane = tid & 31;
    const int g = lane >> 2, t = lane & 3;
    const int wm = warp & 1, wn = warp >> 1;

#pragma unroll
    for (int mt = 0; mt < 4; mt++) {
#pragma unroll
        for (int nt = 0; nt < 4; nt++) {
            const int row0 = mloc + wm * 64 + mt * 16 + g;
            const int col  = nloc + wn * 32 + nt * 8 + 2 * t;
            const float* c = acc[mt][nt];
            float2 gt0 = __half22float2(*(const __half2*)&g_gate[row0 * HIDDEN + col]);
            float2 gt1 = __half22float2(*(const __half2*)&g_gate[(row0 + 8) * HIDDEN + col]);
            float2 y0, y1;
            y0.x = c[0] * Z_SCALE_INV * gt0.x; y0.y = c[1] * Z_SCALE_INV * gt0.y;
            y1.x = c[2] * Z_SCALE_INV * gt1.x; y1.y = c[3] * Z_SCALE_INV * gt1.y;
            *(float2*)&Cout[row0 * HIDDEN + col] = y0;
            *(float2*)&Cout[(row0 + 8) * HIDDEN + col] = y1;
        }
    }
}

// ---------------- preround: convert inputs to fp16 once ----------------
__global__ __launch_bounds__(256)
void preround(const float* __restrict__ hs, const float* __restrict__ Wq,
              const float* __restrict__ Wk, const float* __restrict__ Wv,
              const float* __restrict__ Wo, const float* __restrict__ Wg) {
    constexpr int N_HS = (SEQ * HIDDEN) / 4;          // float4 groups
    constexpr int N_W  = (256 * HIDDEN) / 4;
    constexpr int TOT  = N_HS * 2 + N_W * 4;          // hs, Wg, Wq, Wk, Wv, Wo

    for (int i = blockIdx.x * blockDim.x + threadIdx.x; i < TOT;
         i += gridDim.x * blockDim.x) {
        const float4* src;
        __half* dst;
        int di;
        if (i < N_HS) {
            src = (const float4*)hs + i;            dst = g_hsr;   di = i;
        } else if (i < 2 * N_HS) {
            src = (const float4*)Wg + (i - N_HS);   dst = g_wgr;   di = i - N_HS;
        } else {
            int j = i - 2 * N_HS;
            if (j < N_W)            { src = (const float4*)Wq + j;           dst = g_wqkvr; di = j; }
            else if (j < 2 * N_W)   { src = (const float4*)Wk + (j - N_W);   dst = g_wqkvr; di = j; }
            else if (j < 3 * N_W)   { src = (const float4*)Wv + (j - 2*N_W); dst = g_wqkvr; di = j; }
            else                    { src = (const float4*)Wo + (j - 3*N_W); dst = g_wor;   di = j - 3*N_W; }
        }
        float4 v = *src;
        __half2 h01 = __floats2half2_rn(v.x, v.y);
        __half2 h23 = __floats2half2_rn(v.z, v.w);
        uint2 u;
        u.x = *(uint32_t*)&h01;
        u.y = *(uint32_t*)&h23;
        *(uint2*)&dst[di * 4] = u;
    }
}

// ---------------- windowed decayed-softmax attention ----------------
// decay 0.45 => bias -0.7985*dist; truncation at W=64 leaves < 1e-21 relative mass.
constexpr int WIN = 64, QB = 128;
constexpr int SROWS = QB + WIN - 1;   // 191
constexpr int PITCH = 9;              // conflict-free scalar smem reads

__global__ __launch_bounds__(128)
void attn_kernel(const float* __restrict__ e0, const float* __restrict__ e1) {
    __shared__ float ks[SROWS * PITCH];
    __shared__ float vs[SROWS * PITCH];

    const int h   = blockIdx.y;
    const int q0  = blockIdx.x * QB;
    const int tid = threadIdx.x;
    const int j0  = q0 - (WIN - 1);

    for (int idx = tid; idx < SROWS * 8; idx += 128) {
        const int r = idx >> 3, c = idx & 7;
        const int j = j0 + r;
        float kv = 0.0f, vv = 0.0f;
        if (j >= 0) {
            kv = __half2float(g_qkv[j * QKV_COLS + 256 + h * 8 + c]);
            vv = __half2float(g_qkv[j * QKV_COLS + 512 + h * 8 + c]);
        }
        ks[r * PITCH + c] = kv;
        vs[r * PITCH + c] = vv;
    }
    __syncthreads();

    const int i = q0 + tid;
    float q[8];
#pragma unroll
    for (int b = 0; b < 8; b++) q[b] = __half2float(g_qkv[i * QKV_COLS + h * 8 + b]);

    float num[8];
#pragma unroll
    for (int b = 0; b < 8; b++) num[b] = 0.0f;
    float den = 0.0f;

    const float LOGD = -0.7985077f;   // ln(0.45)
    const int dmax = (i < WIN - 1) ? i : (WIN - 1);

    for (int d = 0; d <= dmax; d++) {
        const int jj = (tid + (WIN - 1) - d) * PITCH;
        float dot = 0.0f;
#pragma unroll
        for (int b = 0; b < 8; b++) dot += q[b] * ks[jj + b];
        const float w = expf(dot * 0.125f + (float)d * LOGD);
        den += w;
#pragma unroll
        for (int b = 0; b < 8; b++) num[b] += w * vs[jj + b];
    }

    const float inv = 1.0f / den;
#pragma unroll
    for (int b = 0; b < 8; b++) {
        const int c = h * 8 + b;
        const float p = num[b] * inv;
        const float z = e1[c] * p + e0[c] * (1.0f - p);
        g_z[i * CDIM + c] = __float2half_rn(z * Z_SCALE);
    }
}

// ---------------- launch ----------------
extern "C" void kernel_launch(void* const* d_in, const int* in_sizes, int n_in,
                              void* d_out, int out_size) {
    const float* hs = (const float*)d_in[0];
    const float* Wq = (const float*)d_in[1];
    const float* Wk = (const float*)d_in[2];
    const float* Wv = (const float*)d_in[3];
    const float* Wo = (const float*)d_in[4];
    const float* Wg = (const float*)d_in[5];
    const float* e0 = (const float*)d_in[6];
    const float* e1 = (const float*)d_in[7];
    float* out = (float*)d_out;

    // 0) convert all GEMM inputs to fp16 once
    preround<<<1024, 256>>>(hs, Wq, Wk, Wv, Wo, Wg);

    // 1) fused QKV projections (+activations) and gate GEMM (+sigmoid)
    gemm_qkv_gate<<<512 + 192, 256>>>();

    // 2) windowed attention + value-embedding interpolation
    attn_kernel<<<dim3(SEQ / QB, NH), 128>>>(e0, e1);

    // 3) out = (z @ Wo^T) * 2^-20 * gate
    gemm_out<<<256, 256>>>(out);
}